// round 16
// baseline (speedup 1.0000x reference)
#include <cuda_runtime.h>
#include <cstdint>

typedef unsigned long long u64;
typedef unsigned int u32;

// ---------------- problem constants ----------------
#define BB 8
#define CC 256
#define NPOS 21824              // per-image positions across 5 maps
#define NANCH 196416            // NPOS * 9
#define KSEL 300
#define NCHUNK 48               // stage1 chunks of 4096 per image
#define NCAND (NCHUNK * KSEL)   // 14400 candidates per image
#define NLOGIT (BB * NPOS * 9)  // 1571328
#define NSEL (BB * KSEL)        // 2400

__device__ __constant__ int c_mapS[5]   = {128, 64, 32, 16, 8};
__device__ __constant__ int c_mapOff[5] = {0, 16384, 20480, 21504, 21760};

// ---------------- device scratch ----------------
__device__ float g_wT[256 * 9 * 256];            // [ic][tap][oc]
__device__ float g_logits2[(size_t)2 * NLOGIT];  // dual-slot, plain stores (no zeroing needed)
__device__ u64   g_cand[(size_t)BB * NCAND];
__device__ u64   g_c2[(size_t)BB * 3 * 512];     // stage-2a outputs: 3 sorted 512-lists/image
__device__ int   g_sel[NSEL];
__device__ int   g_cnt[9];
__device__ int   g_list[9 * NSEL];

// ---------------- f32x2 helpers ----------------
__device__ __forceinline__ u64 dup2(float x) {
    u64 r; asm("mov.b64 %0,{%1,%1};" : "=l"(r) : "f"(x)); return r;
}
__device__ __forceinline__ void ffma2(u64 &c, u64 a, u64 b) {
    asm("fma.rn.f32x2 %0,%1,%2,%3;" : "=l"(c) : "l"(a), "l"(b), "l"(c));
}
__device__ __forceinline__ void fadd2(u64 &c, u64 a) {
    asm("add.rn.f32x2 %0,%1,%2;" : "=l"(c) : "l"(c), "l"(a));
}
__device__ __forceinline__ float2 unpack2(u64 v) {
    float2 f; asm("mov.b64 {%0,%1},%2;" : "=f"(f.x), "=f"(f.y) : "l"(v)); return f;
}

// ---------------- kernel 0: weight transpose + counter zero ----------------
__global__ void k_wtrans(const float* __restrict__ w_pre) {
    int i = blockIdx.x * 1024 + threadIdx.x;   // 576 * 1024 = 589824 exactly
    int oc = i & 255;
    int rest = i >> 8;
    int tap = rest % 9;
    int ic = rest / 9;
    g_wT[i] = w_pre[(oc * 256 + ic) * 9 + tap];
    if (i < 9) g_cnt[i] = 0;
}

// ---------------- kernel 1: conv3x3 + bias + relu + fused 1x1 proj (R9 winner) -------
#define IB_FLOATS 960            // 8*10*12
#define WB_FLOATS 9216           // 8*9*128
#define W_CHUNK_BYTES 73728      // 8*9*256*4

#define LOADROW(dst, rr) { \
    float2 a_ = *(const float2*)(ib + (rr)*12); \
    float2 b_ = *(const float2*)(ib + (rr)*12 + 2); \
    dst[0] = dup2(a_.x); dst[1] = dup2(a_.y); \
    dst[2] = dup2(b_.x); dst[3] = dup2(b_.y); }

#define TAPROW(dy, top, bot) { \
    _Pragma("unroll") \
    for (int dx = 0; dx < 3; ++dx) { \
        const ulonglong2* wp = (const ulonglong2*)(wb + ((dy)*3 + dx) * 128); \
        ulonglong2 wA = wp[0]; \
        ulonglong2 wB = wp[1]; \
        ffma2(ch[0][0], top[dx],   wA.x); ffma2(ch[0][1], top[dx],   wA.y); \
        ffma2(ch[0][2], top[dx],   wB.x); ffma2(ch[0][3], top[dx],   wB.y); \
        ffma2(ch[1][0], top[dx+1], wA.x); ffma2(ch[1][1], top[dx+1], wA.y); \
        ffma2(ch[1][2], top[dx+1], wB.x); ffma2(ch[1][3], top[dx+1], wB.y); \
        ffma2(ch[2][0], bot[dx],   wA.x); ffma2(ch[2][1], bot[dx],   wA.y); \
        ffma2(ch[2][2], bot[dx],   wB.x); ffma2(ch[2][3], bot[dx],   wB.y); \
        ffma2(ch[3][0], bot[dx+1], wA.x); ffma2(ch[3][1], bot[dx+1], wA.y); \
        ffma2(ch[3][2], bot[dx+1], wB.x); ffma2(ch[3][3], bot[dx+1], wB.y); \
    } }

__global__ void __launch_bounds__(256, 2)
k_conv(const float* __restrict__ fm0, const float* __restrict__ fm1,
       const float* __restrict__ fm2, const float* __restrict__ fm3,
       const float* __restrict__ fm4, const float* __restrict__ b_pre,
       const float* __restrict__ w_proj) {
    extern __shared__ float sm[];
    float* ibuf[2] = {sm, sm + IB_FLOATS};
    float* wbuf[2] = {sm + 2 * IB_FLOATS, sm + 2 * IB_FLOATS + WB_FLOATS};
    const u32 smb = (u32)__cvta_generic_to_shared(sm);
    const u32 ibs[2] = {smb, smb + IB_FLOATS * 4};
    const u32 wbs[2] = {smb + 2 * IB_FLOATS * 4, smb + 2 * IB_FLOATS * 4 + WB_FLOATS * 4};

    const int tid = threadIdx.x;
    const int b = blockIdx.y;
    const int zh = blockIdx.z;

    int bx = blockIdx.x, m, tile;
    if (bx < 256)      { m = 0; tile = bx; }
    else if (bx < 320) { m = 1; tile = bx - 256; }
    else if (bx < 336) { m = 2; tile = bx - 320; }
    else if (bx < 340) { m = 3; tile = bx - 336; }
    else               { m = 4; tile = bx - 340; }
    const int s = c_mapS[m];
    const int HW = s * s;
    const int posOff = c_mapOff[m];
    const float* fm = (m == 0) ? fm0 : (m == 1) ? fm1 : (m == 2) ? fm2 : (m == 3) ? fm3 : fm4;

    const int tilesX = s >> 3;
    const int ty0 = (tile / tilesX) << 3;
    const int tx0 = (tile % tilesX) << 3;

    const int pg = tid & 15;
    const int og = tid >> 4;
    const int py = (pg >> 2) << 1;
    const int px = (pg & 3) << 1;

    const char* fb = (const char*)(fm + (size_t)b * 256 * HW);

    bool in_act[4];
    u32  in_so[4], in_go[4], in_sz[4];
#pragma unroll
    for (int k = 0; k < 4; ++k) {
        int idx = tid + (k << 8);
        in_act[k] = (idx < 800);
        int ii = in_act[k] ? idx : 0;
        int ic = ii / 100;
        int rem = ii - ic * 100;
        int r = rem / 10;
        int c = rem - 10 * r;
        int gy = ty0 - 1 + r, gx = tx0 - 1 + c;
        bool ok = (gy >= 0) && (gy < s) && (gx >= 0) && (gx < s);
        in_so[k] = (u32)(((ic * 10 + r) * 12 + c) * 4);
        in_go[k] = ok ? (u32)((ic * HW + gy * s + gx) * 4) : 0u;
        in_sz[k] = ok ? 4u : 0u;
    }
    u32 w_so[9], w_go[9];
#pragma unroll
    for (int k = 0; k < 9; ++k) {
        int i = tid + (k << 8);
        int icL = i / 288;
        int rem = i - icL * 288;
        int tap = rem >> 5;
        int q = rem & 31;
        w_so[k] = (u32)(i * 16);
        w_go[k] = (u32)(((((icL * 9 + tap) << 6) + (zh << 5) + q)) * 16);
    }
    const char* wtb = (const char*)g_wT;

    u64 acc[4][4];
#pragma unroll
    for (int p = 0; p < 4; ++p)
#pragma unroll
        for (int j = 0; j < 4; ++j) acc[p][j] = 0ull;

    {
#pragma unroll
        for (int k = 0; k < 4; ++k) if (in_act[k])
            asm volatile("cp.async.ca.shared.global [%0], [%1], 4, %2;"
                         :: "r"(ibs[0] + in_so[k]), "l"(fb + in_go[k]), "r"(in_sz[k]) : "memory");
#pragma unroll
        for (int k = 0; k < 9; ++k)
            asm volatile("cp.async.cg.shared.global [%0], [%1], 16;"
                         :: "r"(wbs[0] + w_so[k]), "l"(wtb + w_go[k]) : "memory");
        asm volatile("cp.async.commit_group;" ::: "memory");
    }

    const u32 inStride = (u32)(8 * HW * 4);

    for (int cc = 0; cc < 32; ++cc) {
        const int cur = cc & 1;
        asm volatile("cp.async.wait_group 0;" ::: "memory");
        __syncthreads();
        if (cc < 31) {
            const char* f = fb + (size_t)(cc + 1) * inStride;
            const char* w = wtb + (size_t)(cc + 1) * W_CHUNK_BYTES;
            const u32 ibS = ibs[cur ^ 1], wbS = wbs[cur ^ 1];
#pragma unroll
            for (int k = 0; k < 4; ++k) if (in_act[k])
                asm volatile("cp.async.ca.shared.global [%0], [%1], 4, %2;"
                             :: "r"(ibS + in_so[k]), "l"(f + in_go[k]), "r"(in_sz[k]) : "memory");
#pragma unroll
            for (int k = 0; k < 9; ++k)
                asm volatile("cp.async.cg.shared.global [%0], [%1], 16;"
                             :: "r"(wbS + w_so[k]), "l"(w + w_go[k]) : "memory");
            asm volatile("cp.async.commit_group;" ::: "memory");
        }

        u64 ch[4][4];
#pragma unroll
        for (int p = 0; p < 4; ++p)
#pragma unroll
            for (int j = 0; j < 4; ++j) ch[p][j] = 0ull;

        const float* ibase = ibuf[cur] + py * 12 + px;
        const float* wbase2 = wbuf[cur] + og * 8;
#pragma unroll
        for (int ic = 0; ic < 8; ++ic) {
            const float* ib = ibase + ic * 120;
            const float* wb = wbase2 + ic * 1152;
            u64 rA[4], rB[4];
            LOADROW(rA, 0);
            LOADROW(rB, 1);
            TAPROW(0, rA, rB);
            LOADROW(rA, 2);
            TAPROW(1, rB, rA);
            LOADROW(rB, 3);
            TAPROW(2, rA, rB);
        }
#pragma unroll
        for (int p = 0; p < 4; ++p)
#pragma unroll
            for (int j = 0; j < 4; ++j) fadd2(acc[p][j], ch[p][j]);
    }

    // ---- fused epilogue: bias + relu + 1x1 proj partials ----
    float part[4][9];
#pragma unroll
    for (int p = 0; p < 4; ++p)
#pragma unroll
        for (int a = 0; a < 9; ++a) part[p][a] = 0.f;

#pragma unroll
    for (int j = 0; j < 4; ++j) {
        const int oc = zh * 128 + og * 8 + 2 * j;
        const float b0 = b_pre[oc], b1 = b_pre[oc + 1];
#pragma unroll
        for (int p = 0; p < 4; ++p) {
            float2 v = unpack2(acc[p][j]);
            float r0 = fmaxf(v.x + b0, 0.f);
            float r1 = fmaxf(v.y + b1, 0.f);
#pragma unroll
            for (int a = 0; a < 9; ++a) {
                float t = part[p][a];
                t = fmaf(r0, w_proj[a * 256 + oc], t);
                t = fmaf(r1, w_proj[a * 256 + oc + 1], t);
                part[p][a] = t;
            }
        }
    }

    float* red = wbuf[0];
#pragma unroll
    for (int p = 0; p < 4; ++p) {
        int pl = (py + (p >> 1)) * 8 + (px + (p & 1));
#pragma unroll
        for (int a = 0; a < 9; ++a)
            red[(og * 64 + pl) * 9 + a] = part[p][a];
    }
    __syncthreads();

    // reduce over og in fixed ascending order -> PLAIN STORE into this half's slot
    // (each (b,pos,a,zh) is written by exactly one block: no race, no zeroing)
    float* lslot = g_logits2 + (size_t)zh * NLOGIT;
    for (int item = tid; item < 576; item += 256) {
        int pl = item / 9;
        int a = item - 9 * pl;
        float v = 0.f;
#pragma unroll
        for (int o = 0; o < 16; ++o)
            v += red[(o * 64 + pl) * 9 + a];
        int gy = ty0 + (pl >> 3);
        int gx = tx0 + (pl & 7);
        int pos = posOff + gy * s + gx;
        lslot[((size_t)b * NPOS + pos) * 9 + a] = v;
    }
}

// ---------------- warp-level bitonic sort (descending) of 256 keys, 8/lane ----------
__device__ __forceinline__ void warp_sort256_desc(u64 v[8], int lane) {
#pragma unroll
    for (int k = 2; k <= 256; k <<= 1) {
#pragma unroll
        for (int j = k >> 1; j > 0; j >>= 1) {
            if (j >= 32) {
                const int jr = j >> 5;
#pragma unroll
                for (int r = 0; r < 8; ++r) {
                    if ((r & jr) == 0) {
                        const int r2 = r | jr;
                        const bool wantmax = (((r * 32) & k) == 0);
                        u64 a = v[r], bq = v[r2];
                        u64 mx = a > bq ? a : bq;
                        u64 mn = a > bq ? bq : a;
                        v[r]  = wantmax ? mx : mn;
                        v[r2] = wantmax ? mn : mx;
                    }
                }
            } else {
#pragma unroll
                for (int r = 0; r < 8; ++r) {
                    u64 p = __shfl_xor_sync(0xFFFFFFFFu, v[r], j);
                    const int eak = (k >= 32) ? ((r * 32) & k) : (lane & k);
                    const bool wantmax = (eak == 0);
                    const bool is_low = ((lane & j) == 0);
                    const bool takemax = (is_low == wantmax);
                    u64 mx = v[r] > p ? v[r] : p;
                    u64 mn = v[r] > p ? p : v[r];
                    v[r] = takemax ? mx : mn;
                }
            }
        }
    }
}

// ---------------- kernel 3: stage1 — keys inline + warp sort + tournament top-300 ----
__global__ void __launch_bounds__(512)
k_top1(const float* __restrict__ b_proj) {
    __shared__ u64 sk[4096];
    const int tid = threadIdx.x;
    const int lane = tid & 31;
    const int w = tid >> 5;
    const int blk = blockIdx.x;
    const int b = blockIdx.y;
    const float* lg0 = g_logits2 + (size_t)b * NPOS * 9;
    const float* lg1 = g_logits2 + (size_t)NLOGIT + (size_t)b * NPOS * 9;

    u64 v[8];
#pragma unroll
    for (int r = 0; r < 8; ++r) {
        int aidx = blk * 4096 + w * 256 + r * 32 + lane;
        u64 key = 0ull;
        if (aidx < NANCH) {
            int p = aidx / 9;
            int a = aidx - 9 * p;
            float logit = (lg0[aidx] + lg1[aidx]) + b_proj[a];  // == commutative atomic sum
            float prob = 1.0f / (1.0f + expf(-logit));
            u32 pb = __float_as_uint(prob);
            key = ((u64)pb << 32) | (u64)(0xFFFFFFFFu - (u32)aidx);
        }
        v[r] = key;
    }
    warp_sort256_desc(v, lane);
#pragma unroll
    for (int r = 0; r < 8; ++r)
        sk[w * 256 + r * 32 + lane] = v[r];
    __syncthreads();

    // Full merge 16x256 -> 8x512
    {
        u64 tv[8];
        int c = 0;
        for (int x = tid; x < 4096; x += 512, ++c) {
            int sseg = x >> 9, i = x & 511;
            tv[c] = (i < 256) ? sk[(2 * sseg) * 256 + i]
                              : sk[(2 * sseg + 1) * 256 + (511 - i)];
        }
        __syncthreads();
        c = 0;
        for (int x = tid; x < 4096; x += 512, ++c) sk[x] = tv[c];
        for (int j = 256; j > 0; j >>= 1) {
            __syncthreads();
            for (int t = tid; t < 2048; t += 512) {
                int seg = t >> 8, off = t & 255;
                int i = seg * 512 + (((off & ~(j - 1)) << 1) | (off & (j - 1)));
                u64 x = sk[i], y = sk[i + j];
                if (x < y) { sk[i] = y; sk[i + j] = x; }
            }
        }
    }

    // Phase B: tournament merge rounds
    for (int half = 4; half >= 1; half >>= 1) {
        const int nel = half * 512;
        __syncthreads();
        u64 va[4], vb[4];
        int cnt = 0;
        for (int e = tid; e < nel; e += 512, ++cnt) {
            int seg = e >> 9, i = e & 511;
            va[cnt] = sk[(seg * 2) * 512 + i];
            vb[cnt] = sk[(seg * 2 + 1) * 512 + 511 - i];
        }
        __syncthreads();
        cnt = 0;
        for (int e = tid; e < nel; e += 512, ++cnt)
            sk[e] = (va[cnt] > vb[cnt]) ? va[cnt] : vb[cnt];
        for (int j = 256; j > 0; j >>= 1) {
            __syncthreads();
            for (int c = tid; c < half * 256; c += 512) {
                int seg = c >> 8, off = c & 255;
                int i = seg * 512 + (((off & ~(j - 1)) << 1) | (off & (j - 1)));
                u64 x = sk[i], y = sk[i + j];
                if (x < y) { sk[i] = y; sk[i + j] = x; }
            }
        }
    }
    __syncthreads();

    u64* dst = g_cand + ((size_t)b * NCHUNK + blk) * KSEL;
    for (int i = tid; i < KSEL; i += 512) dst[i] = sk[i];
}

// ---------------- kernel 4a: stage2a — each block merges 16 sorted lists -> top-512 --
__device__ __forceinline__ void t2_clean(u64* sk, int nseg, int tid, int nthr) {
    for (int j = 256; j > 0; j >>= 1) {
        __syncthreads();
        for (int c = tid; c < nseg * 256; c += nthr) {
            int seg = c >> 8, off = c & 255;
            int i = seg * 512 + (((off & ~(j - 1)) << 1) | (off & (j - 1)));
            u64 x = sk[i], y = sk[i + j];
            if (x < y) { sk[i] = y; sk[i + j] = x; }
        }
    }
}

__global__ void __launch_bounds__(1024)
k_top2a() {
    extern __shared__ u64 sk2[];   // 8 * 512 keys = 32 KB
    const int tid = threadIdx.x;
    const int grp = blockIdx.x;    // 0..2
    const int b = blockIdx.y;
    const u64* src = g_cand + (size_t)b * NCAND + (size_t)grp * 16 * KSEL;

    for (int e = tid; e < 8 * 512; e += 1024) {
        int seg = e >> 9, i = e & 511;
        u64 a = (i < KSEL) ? src[(seg * 2) * KSEL + i] : 0ull;
        int ri = 511 - i;
        u64 c = (ri < KSEL) ? src[(seg * 2 + 1) * KSEL + ri] : 0ull;
        sk2[e] = (a > c) ? a : c;
    }
    t2_clean(sk2, 8, tid, 1024);

    for (int nsegO = 4; nsegO >= 1; nsegO >>= 1) {
        const int nel = nsegO * 512;
        __syncthreads();
        u64 va[2], vb[2];
        int cnt = 0;
        for (int e = tid; e < nel; e += 1024, ++cnt) {
            int seg = e >> 9, i = e & 511;
            va[cnt] = sk2[(seg * 2) * 512 + i];
            vb[cnt] = sk2[(seg * 2 + 1) * 512 + 511 - i];
        }
        __syncthreads();
        cnt = 0;
        for (int e = tid; e < nel; e += 1024, ++cnt)
            sk2[e] = (va[cnt] > vb[cnt]) ? va[cnt] : vb[cnt];
        t2_clean(sk2, nsegO, tid, 1024);
    }
    __syncthreads();

    u64* dst = g_c2 + ((size_t)b * 3 + grp) * 512;
    for (int i = tid; i < 512; i += 1024) dst[i] = sk2[i];
}

// ---------------- kernel 4b: stage2b — merge 3 sorted 512-lists, emit + group -------
__global__ void __launch_bounds__(512)
k_top2b() {
    __shared__ u64 sk[512];
    const int tid = threadIdx.x;
    const int b = blockIdx.x;
    const u64* src = g_c2 + (size_t)b * 3 * 512;

    sk[tid] = src[tid];
    for (int other = 1; other <= 2; ++other) {
        __syncthreads();
        u64 va = sk[tid];
        u64 vb = src[other * 512 + 511 - tid];
        __syncthreads();
        sk[tid] = (va > vb) ? va : vb;
        for (int j = 256; j > 0; j >>= 1) {
            __syncthreads();
            if (tid < 256) {
                int i = ((tid & ~(j - 1)) << 1) | (tid & (j - 1));
                u64 x = sk[i], y = sk[i + j];
                if (x < y) { sk[i] = y; sk[i + j] = x; }
            }
        }
    }
    __syncthreads();

    if (tid < KSEL) {
        int sel = (int)(0xFFFFFFFFu - (u32)(sk[tid] & 0xFFFFFFFFull));
        int n = b * KSEL + tid;
        g_sel[n] = sel;
        int a = sel % 9;
        int slot = atomicAdd(&g_cnt[a], 1);
        g_list[a * NSEL + slot] = n;
    }
}

// ---------------- kernel 5: anchor-grouped gather + 256x256 matvec (16 rows/block) ---
__global__ void __launch_bounds__(256)
k_post(const float* __restrict__ fm0, const float* __restrict__ fm1,
       const float* __restrict__ fm2, const float* __restrict__ fm3,
       const float* __restrict__ fm4, const float* __restrict__ w_post,
       const float* __restrict__ b_post, float* __restrict__ out) {
    __shared__ float xs[16 * 256];
    const int a = blockIdx.y;
    const int start = blockIdx.x * 16;
    const int cnt = g_cnt[a];
    if (start >= cnt) return;
    const int tid = threadIdx.x;
    const int nr = min(16, cnt - start);

#pragma unroll
    for (int r = 0; r < 16; ++r) xs[r * 256 + tid] = 0.f;

    int rows[16];
    for (int r = 0; r < nr; ++r) {
        int n = g_list[a * NSEL + start + r];
        rows[r] = n;
        int b = n / KSEL;
        int pos = g_sel[n] / 9;
        int m, hw, HW;
        if (pos < 16384)      { m = 0; hw = pos;         HW = 16384; }
        else if (pos < 20480) { m = 1; hw = pos - 16384; HW = 4096;  }
        else if (pos < 21504) { m = 2; hw = pos - 20480; HW = 1024;  }
        else if (pos < 21760) { m = 3; hw = pos - 21504; HW = 256;   }
        else                  { m = 4; hw = pos - 21760; HW = 64;    }
        const float* fm = (m == 0) ? fm0 : (m == 1) ? fm1 : (m == 2) ? fm2 : (m == 3) ? fm3 : fm4;
        xs[r * 256 + tid] = fm[((size_t)b * 256 + tid) * HW + hw];
    }
    __syncthreads();

    const float* W = w_post + (size_t)a * 65536;
    const float bb = b_post[a * 256 + tid];
    float acc[16];
#pragma unroll
    for (int r = 0; r < 16; ++r) acc[r] = bb;

#pragma unroll 2
    for (int d = 0; d < 256; ++d) {
        float w = W[d * 256 + tid];
#pragma unroll
        for (int r = 0; r < 16; ++r)
            acc[r] = fmaf(xs[r * 256 + d], w, acc[r]);
    }
    for (int r = 0; r < nr; ++r)
        out[(size_t)rows[r] * 256 + tid] = acc[r];
}

// ---------------- launch ----------------
extern "C" void kernel_launch(void* const* d_in, const int* in_sizes, int n_in,
                              void* d_out, int out_size) {
    const float* fm[5];
    for (int i = 0; i < 5; ++i) fm[i] = (const float*)d_in[i];
    const float* w_pre  = (const float*)d_in[5];
    const float* b_pre  = (const float*)d_in[6];
    const float* w_proj = (const float*)d_in[7];
    const float* b_proj = (const float*)d_in[8];
    const float* w_post = (const float*)d_in[9];
    const float* b_post = (const float*)d_in[10];
    float* out = (float*)d_out;

    const int convSmem = (2 * IB_FLOATS + 2 * WB_FLOATS) * 4;   // 81408 B
    const int top2aSmem = 8 * 512 * 8;                          // 32768 B
    cudaFuncSetAttribute(k_conv, cudaFuncAttributeMaxDynamicSharedMemorySize, convSmem);
    cudaFuncSetAttribute(k_top2a, cudaFuncAttributeMaxDynamicSharedMemorySize, top2aSmem);

    k_wtrans<<<576, 1024>>>(w_pre);

    {
        dim3 grid(341, BB, 2);   // tiles x batch x oc-half
        k_conv<<<grid, 256, convSmem>>>(fm[0], fm[1], fm[2], fm[3], fm[4], b_pre, w_proj);
    }
    {
        dim3 grid(NCHUNK, BB);
        k_top1<<<grid, 512>>>(b_proj);
    }
    {
        dim3 grid(3, BB);
        k_top2a<<<grid, 1024, top2aSmem>>>();
    }
    k_top2b<<<BB, 512>>>();
    {
        dim3 grid((NSEL + 15) / 16, 9);
        k_post<<<grid, 256>>>(fm[0], fm[1], fm[2], fm[3], fm[4], w_post, b_post, out);
    }
}

// round 17
// speedup vs baseline: 1.0013x; 1.0013x over previous
#include <cuda_runtime.h>
#include <cstdint>

typedef unsigned long long u64;
typedef unsigned int u32;

// ---------------- problem constants ----------------
#define BB 8
#define CC 256
#define NPOS 21824              // per-image positions across 5 maps
#define NANCH 196416            // NPOS * 9
#define KSEL 300
#define NCHUNK 48               // stage1 chunks of 4096 per image
#define NCAND (NCHUNK * KSEL)   // 14400 candidates per image
#define NLOGIT (BB * NPOS * 9)  // 1571328
#define NSEL (BB * KSEL)        // 2400

__device__ __constant__ int c_mapS[5]   = {128, 64, 32, 16, 8};
__device__ __constant__ int c_mapOff[5] = {0, 16384, 20480, 21504, 21760};

// ---------------- device scratch ----------------
__device__ float g_wT[256 * 9 * 256];            // [ic][tap][oc]
__device__ float g_logits[(size_t)NLOGIT];       // fused proj output (2-way atomic, commutative)
__device__ u64   g_cand[(size_t)BB * NCAND];
__device__ u64   g_c2[(size_t)BB * 3 * 512];     // stage-2a outputs: 3 sorted 512-lists/image
__device__ int   g_sel[NSEL];
__device__ int   g_cnt[9];
__device__ int   g_list[9 * NSEL];

// ---------------- f32x2 helpers ----------------
__device__ __forceinline__ u64 dup2(float x) {
    u64 r; asm("mov.b64 %0,{%1,%1};" : "=l"(r) : "f"(x)); return r;
}
__device__ __forceinline__ void ffma2(u64 &c, u64 a, u64 b) {
    asm("fma.rn.f32x2 %0,%1,%2,%3;" : "=l"(c) : "l"(a), "l"(b), "l"(c));
}
__device__ __forceinline__ void fadd2(u64 &c, u64 a) {
    asm("add.rn.f32x2 %0,%1,%2;" : "=l"(c) : "l"(c), "l"(a));
}
__device__ __forceinline__ float2 unpack2(u64 v) {
    float2 f; asm("mov.b64 {%0,%1},%2;" : "=f"(f.x), "=f"(f.y) : "l"(v)); return f;
}

// ---------------- kernel 0: weight transpose + logit zero (float4) + counters -------
__global__ void k_wtrans(const float* __restrict__ w_pre) {
    int i = blockIdx.x * 1024 + threadIdx.x;   // 576 * 1024 = 589824 exactly
    int oc = i & 255;
    int rest = i >> 8;
    int tap = rest % 9;
    int ic = rest / 9;
    g_wT[i] = w_pre[(oc * 256 + ic) * 9 + tap];
    if (i < NLOGIT / 4)                        // 392832 float4 = 1571328 floats
        ((float4*)g_logits)[i] = make_float4(0.f, 0.f, 0.f, 0.f);
    if (i < 9) g_cnt[i] = 0;
}

// ---------------- kernel 1: conv3x3 + bias + relu + fused 1x1 proj (R9 winner) -------
#define IB_FLOATS 960            // 8*10*12
#define WB_FLOATS 9216           // 8*9*128
#define W_CHUNK_BYTES 73728      // 8*9*256*4

#define LOADROW(dst, rr) { \
    float2 a_ = *(const float2*)(ib + (rr)*12); \
    float2 b_ = *(const float2*)(ib + (rr)*12 + 2); \
    dst[0] = dup2(a_.x); dst[1] = dup2(a_.y); \
    dst[2] = dup2(b_.x); dst[3] = dup2(b_.y); }

#define TAPROW(dy, top, bot) { \
    _Pragma("unroll") \
    for (int dx = 0; dx < 3; ++dx) { \
        const ulonglong2* wp = (const ulonglong2*)(wb + ((dy)*3 + dx) * 128); \
        ulonglong2 wA = wp[0]; \
        ulonglong2 wB = wp[1]; \
        ffma2(ch[0][0], top[dx],   wA.x); ffma2(ch[0][1], top[dx],   wA.y); \
        ffma2(ch[0][2], top[dx],   wB.x); ffma2(ch[0][3], top[dx],   wB.y); \
        ffma2(ch[1][0], top[dx+1], wA.x); ffma2(ch[1][1], top[dx+1], wA.y); \
        ffma2(ch[1][2], top[dx+1], wB.x); ffma2(ch[1][3], top[dx+1], wB.y); \
        ffma2(ch[2][0], bot[dx],   wA.x); ffma2(ch[2][1], bot[dx],   wA.y); \
        ffma2(ch[2][2], bot[dx],   wB.x); ffma2(ch[2][3], bot[dx],   wB.y); \
        ffma2(ch[3][0], bot[dx+1], wA.x); ffma2(ch[3][1], bot[dx+1], wA.y); \
        ffma2(ch[3][2], bot[dx+1], wB.x); ffma2(ch[3][3], bot[dx+1], wB.y); \
    } }

__global__ void __launch_bounds__(256, 2)
k_conv(const float* __restrict__ fm0, const float* __restrict__ fm1,
       const float* __restrict__ fm2, const float* __restrict__ fm3,
       const float* __restrict__ fm4, const float* __restrict__ b_pre,
       const float* __restrict__ w_proj) {
    extern __shared__ float sm[];
    float* ibuf[2] = {sm, sm + IB_FLOATS};
    float* wbuf[2] = {sm + 2 * IB_FLOATS, sm + 2 * IB_FLOATS + WB_FLOATS};
    const u32 smb = (u32)__cvta_generic_to_shared(sm);
    const u32 ibs[2] = {smb, smb + IB_FLOATS * 4};
    const u32 wbs[2] = {smb + 2 * IB_FLOATS * 4, smb + 2 * IB_FLOATS * 4 + WB_FLOATS * 4};

    const int tid = threadIdx.x;
    const int b = blockIdx.y;
    const int zh = blockIdx.z;

    int bx = blockIdx.x, m, tile;
    if (bx < 256)      { m = 0; tile = bx; }
    else if (bx < 320) { m = 1; tile = bx - 256; }
    else if (bx < 336) { m = 2; tile = bx - 320; }
    else if (bx < 340) { m = 3; tile = bx - 336; }
    else               { m = 4; tile = bx - 340; }
    const int s = c_mapS[m];
    const int HW = s * s;
    const int posOff = c_mapOff[m];
    const float* fm = (m == 0) ? fm0 : (m == 1) ? fm1 : (m == 2) ? fm2 : (m == 3) ? fm3 : fm4;

    const int tilesX = s >> 3;
    const int ty0 = (tile / tilesX) << 3;
    const int tx0 = (tile % tilesX) << 3;

    const int pg = tid & 15;
    const int og = tid >> 4;
    const int py = (pg >> 2) << 1;
    const int px = (pg & 3) << 1;

    const char* fb = (const char*)(fm + (size_t)b * 256 * HW);

    bool in_act[4];
    u32  in_so[4], in_go[4], in_sz[4];
#pragma unroll
    for (int k = 0; k < 4; ++k) {
        int idx = tid + (k << 8);
        in_act[k] = (idx < 800);
        int ii = in_act[k] ? idx : 0;
        int ic = ii / 100;
        int rem = ii - ic * 100;
        int r = rem / 10;
        int c = rem - 10 * r;
        int gy = ty0 - 1 + r, gx = tx0 - 1 + c;
        bool ok = (gy >= 0) && (gy < s) && (gx >= 0) && (gx < s);
        in_so[k] = (u32)(((ic * 10 + r) * 12 + c) * 4);
        in_go[k] = ok ? (u32)((ic * HW + gy * s + gx) * 4) : 0u;
        in_sz[k] = ok ? 4u : 0u;
    }
    u32 w_so[9], w_go[9];
#pragma unroll
    for (int k = 0; k < 9; ++k) {
        int i = tid + (k << 8);
        int icL = i / 288;
        int rem = i - icL * 288;
        int tap = rem >> 5;
        int q = rem & 31;
        w_so[k] = (u32)(i * 16);
        w_go[k] = (u32)(((((icL * 9 + tap) << 6) + (zh << 5) + q)) * 16);
    }
    const char* wtb = (const char*)g_wT;

    u64 acc[4][4];
#pragma unroll
    for (int p = 0; p < 4; ++p)
#pragma unroll
        for (int j = 0; j < 4; ++j) acc[p][j] = 0ull;

    {
#pragma unroll
        for (int k = 0; k < 4; ++k) if (in_act[k])
            asm volatile("cp.async.ca.shared.global [%0], [%1], 4, %2;"
                         :: "r"(ibs[0] + in_so[k]), "l"(fb + in_go[k]), "r"(in_sz[k]) : "memory");
#pragma unroll
        for (int k = 0; k < 9; ++k)
            asm volatile("cp.async.cg.shared.global [%0], [%1], 16;"
                         :: "r"(wbs[0] + w_so[k]), "l"(wtb + w_go[k]) : "memory");
        asm volatile("cp.async.commit_group;" ::: "memory");
    }

    const u32 inStride = (u32)(8 * HW * 4);

    for (int cc = 0; cc < 32; ++cc) {
        const int cur = cc & 1;
        asm volatile("cp.async.wait_group 0;" ::: "memory");
        __syncthreads();
        if (cc < 31) {
            const char* f = fb + (size_t)(cc + 1) * inStride;
            const char* w = wtb + (size_t)(cc + 1) * W_CHUNK_BYTES;
            const u32 ibS = ibs[cur ^ 1], wbS = wbs[cur ^ 1];
#pragma unroll
            for (int k = 0; k < 4; ++k) if (in_act[k])
                asm volatile("cp.async.ca.shared.global [%0], [%1], 4, %2;"
                             :: "r"(ibS + in_so[k]), "l"(f + in_go[k]), "r"(in_sz[k]) : "memory");
#pragma unroll
            for (int k = 0; k < 9; ++k)
                asm volatile("cp.async.cg.shared.global [%0], [%1], 16;"
                             :: "r"(wbS + w_so[k]), "l"(w + w_go[k]) : "memory");
            asm volatile("cp.async.commit_group;" ::: "memory");
        }

        u64 ch[4][4];
#pragma unroll
        for (int p = 0; p < 4; ++p)
#pragma unroll
            for (int j = 0; j < 4; ++j) ch[p][j] = 0ull;

        const float* ibase = ibuf[cur] + py * 12 + px;
        const float* wbase2 = wbuf[cur] + og * 8;
#pragma unroll
        for (int ic = 0; ic < 8; ++ic) {
            const float* ib = ibase + ic * 120;
            const float* wb = wbase2 + ic * 1152;
            u64 rA[4], rB[4];
            LOADROW(rA, 0);
            LOADROW(rB, 1);
            TAPROW(0, rA, rB);
            LOADROW(rA, 2);
            TAPROW(1, rB, rA);
            LOADROW(rB, 3);
            TAPROW(2, rA, rB);
        }
#pragma unroll
        for (int p = 0; p < 4; ++p)
#pragma unroll
            for (int j = 0; j < 4; ++j) fadd2(acc[p][j], ch[p][j]);
    }

    // ---- fused epilogue: bias + relu + 1x1 proj partials ----
    float part[4][9];
#pragma unroll
    for (int p = 0; p < 4; ++p)
#pragma unroll
        for (int a = 0; a < 9; ++a) part[p][a] = 0.f;

#pragma unroll
    for (int j = 0; j < 4; ++j) {
        const int oc = zh * 128 + og * 8 + 2 * j;
        const float b0 = b_pre[oc], b1 = b_pre[oc + 1];
#pragma unroll
        for (int p = 0; p < 4; ++p) {
            float2 v = unpack2(acc[p][j]);
            float r0 = fmaxf(v.x + b0, 0.f);
            float r1 = fmaxf(v.y + b1, 0.f);
#pragma unroll
            for (int a = 0; a < 9; ++a) {
                float t = part[p][a];
                t = fmaf(r0, w_proj[a * 256 + oc], t);
                t = fmaf(r1, w_proj[a * 256 + oc + 1], t);
                part[p][a] = t;
            }
        }
    }

    float* red = wbuf[0];
#pragma unroll
    for (int p = 0; p < 4; ++p) {
        int pl = (py + (p >> 1)) * 8 + (px + (p & 1));
#pragma unroll
        for (int a = 0; a < 9; ++a)
            red[(og * 64 + pl) * 9 + a] = part[p][a];
    }
    __syncthreads();

    // reduce over og in fixed ascending order -> atomicAdd (2 commutative adds/logit)
    for (int item = tid; item < 576; item += 256) {
        int pl = item / 9;
        int a = item - 9 * pl;
        float v = 0.f;
#pragma unroll
        for (int o = 0; o < 16; ++o)
            v += red[(o * 64 + pl) * 9 + a];
        int gy = ty0 + (pl >> 3);
        int gx = tx0 + (pl & 7);
        int pos = posOff + gy * s + gx;
        atomicAdd(&g_logits[((size_t)b * NPOS + pos) * 9 + a], v);
    }
}

// ---------------- warp-level bitonic sort (descending) of 256 keys, 8/lane ----------
__device__ __forceinline__ void warp_sort256_desc(u64 v[8], int lane) {
#pragma unroll
    for (int k = 2; k <= 256; k <<= 1) {
#pragma unroll
        for (int j = k >> 1; j > 0; j >>= 1) {
            if (j >= 32) {
                const int jr = j >> 5;
#pragma unroll
                for (int r = 0; r < 8; ++r) {
                    if ((r & jr) == 0) {
                        const int r2 = r | jr;
                        const bool wantmax = (((r * 32) & k) == 0);
                        u64 a = v[r], bq = v[r2];
                        u64 mx = a > bq ? a : bq;
                        u64 mn = a > bq ? bq : a;
                        v[r]  = wantmax ? mx : mn;
                        v[r2] = wantmax ? mn : mx;
                    }
                }
            } else {
#pragma unroll
                for (int r = 0; r < 8; ++r) {
                    u64 p = __shfl_xor_sync(0xFFFFFFFFu, v[r], j);
                    const int eak = (k >= 32) ? ((r * 32) & k) : (lane & k);
                    const bool wantmax = (eak == 0);
                    const bool is_low = ((lane & j) == 0);
                    const bool takemax = (is_low == wantmax);
                    u64 mx = v[r] > p ? v[r] : p;
                    u64 mn = v[r] > p ? p : v[r];
                    v[r] = takemax ? mx : mn;
                }
            }
        }
    }
}

// ---------------- kernel 3: stage1 — keys inline + warp sort + tournament top-300 ----
__global__ void __launch_bounds__(512)
k_top1(const float* __restrict__ b_proj) {
    __shared__ u64 sk[4096];
    const int tid = threadIdx.x;
    const int lane = tid & 31;
    const int w = tid >> 5;
    const int blk = blockIdx.x;
    const int b = blockIdx.y;
    const float* lg = g_logits + (size_t)b * NPOS * 9;

    u64 v[8];
#pragma unroll
    for (int r = 0; r < 8; ++r) {
        int aidx = blk * 4096 + w * 256 + r * 32 + lane;
        u64 key = 0ull;
        if (aidx < NANCH) {
            int p = aidx / 9;
            int a = aidx - 9 * p;
            float logit = lg[aidx] + b_proj[a];
            float prob = 1.0f / (1.0f + expf(-logit));
            u32 pb = __float_as_uint(prob);
            key = ((u64)pb << 32) | (u64)(0xFFFFFFFFu - (u32)aidx);
        }
        v[r] = key;
    }
    warp_sort256_desc(v, lane);
#pragma unroll
    for (int r = 0; r < 8; ++r)
        sk[w * 256 + r * 32 + lane] = v[r];
    __syncthreads();

    // Full merge 16x256 -> 8x512
    {
        u64 tv[8];
        int c = 0;
        for (int x = tid; x < 4096; x += 512, ++c) {
            int sseg = x >> 9, i = x & 511;
            tv[c] = (i < 256) ? sk[(2 * sseg) * 256 + i]
                              : sk[(2 * sseg + 1) * 256 + (511 - i)];
        }
        __syncthreads();
        c = 0;
        for (int x = tid; x < 4096; x += 512, ++c) sk[x] = tv[c];
        for (int j = 256; j > 0; j >>= 1) {
            __syncthreads();
            for (int t = tid; t < 2048; t += 512) {
                int seg = t >> 8, off = t & 255;
                int i = seg * 512 + (((off & ~(j - 1)) << 1) | (off & (j - 1)));
                u64 x = sk[i], y = sk[i + j];
                if (x < y) { sk[i] = y; sk[i + j] = x; }
            }
        }
    }

    // Phase B: tournament merge rounds
    for (int half = 4; half >= 1; half >>= 1) {
        const int nel = half * 512;
        __syncthreads();
        u64 va[4], vb[4];
        int cnt = 0;
        for (int e = tid; e < nel; e += 512, ++cnt) {
            int seg = e >> 9, i = e & 511;
            va[cnt] = sk[(seg * 2) * 512 + i];
            vb[cnt] = sk[(seg * 2 + 1) * 512 + 511 - i];
        }
        __syncthreads();
        cnt = 0;
        for (int e = tid; e < nel; e += 512, ++cnt)
            sk[e] = (va[cnt] > vb[cnt]) ? va[cnt] : vb[cnt];
        for (int j = 256; j > 0; j >>= 1) {
            __syncthreads();
            for (int c = tid; c < half * 256; c += 512) {
                int seg = c >> 8, off = c & 255;
                int i = seg * 512 + (((off & ~(j - 1)) << 1) | (off & (j - 1)));
                u64 x = sk[i], y = sk[i + j];
                if (x < y) { sk[i] = y; sk[i + j] = x; }
            }
        }
    }
    __syncthreads();

    u64* dst = g_cand + ((size_t)b * NCHUNK + blk) * KSEL;
    for (int i = tid; i < KSEL; i += 512) dst[i] = sk[i];
}

// ---------------- kernel 4a: stage2a — each block merges 16 sorted lists -> top-512 --
__device__ __forceinline__ void t2_clean(u64* sk, int nseg, int tid, int nthr) {
    for (int j = 256; j > 0; j >>= 1) {
        __syncthreads();
        for (int c = tid; c < nseg * 256; c += nthr) {
            int seg = c >> 8, off = c & 255;
            int i = seg * 512 + (((off & ~(j - 1)) << 1) | (off & (j - 1)));
            u64 x = sk[i], y = sk[i + j];
            if (x < y) { sk[i] = y; sk[i + j] = x; }
        }
    }
}

__global__ void __launch_bounds__(1024)
k_top2a() {
    extern __shared__ u64 sk2[];   // 8 * 512 keys = 32 KB
    const int tid = threadIdx.x;
    const int grp = blockIdx.x;    // 0..2
    const int b = blockIdx.y;
    const u64* src = g_cand + (size_t)b * NCAND + (size_t)grp * 16 * KSEL;

    for (int e = tid; e < 8 * 512; e += 1024) {
        int seg = e >> 9, i = e & 511;
        u64 a = (i < KSEL) ? src[(seg * 2) * KSEL + i] : 0ull;
        int ri = 511 - i;
        u64 c = (ri < KSEL) ? src[(seg * 2 + 1) * KSEL + ri] : 0ull;
        sk2[e] = (a > c) ? a : c;
    }
    t2_clean(sk2, 8, tid, 1024);

    for (int nsegO = 4; nsegO >= 1; nsegO >>= 1) {
        const int nel = nsegO * 512;
        __syncthreads();
        u64 va[2], vb[2];
        int cnt = 0;
        for (int e = tid; e < nel; e += 1024, ++cnt) {
            int seg = e >> 9, i = e & 511;
            va[cnt] = sk2[(seg * 2) * 512 + i];
            vb[cnt] = sk2[(seg * 2 + 1) * 512 + 511 - i];
        }
        __syncthreads();
        cnt = 0;
        for (int e = tid; e < nel; e += 1024, ++cnt)
            sk2[e] = (va[cnt] > vb[cnt]) ? va[cnt] : vb[cnt];
        t2_clean(sk2, nsegO, tid, 1024);
    }
    __syncthreads();

    u64* dst = g_c2 + ((size_t)b * 3 + grp) * 512;
    for (int i = tid; i < 512; i += 1024) dst[i] = sk2[i];
}

// ---------------- kernel 4b: stage2b — merge 3 sorted 512-lists, emit + group -------
__global__ void __launch_bounds__(512)
k_top2b() {
    __shared__ u64 sk[512];
    const int tid = threadIdx.x;
    const int b = blockIdx.x;
    const u64* src = g_c2 + (size_t)b * 3 * 512;

    sk[tid] = src[tid];
    for (int other = 1; other <= 2; ++other) {
        __syncthreads();
        u64 va = sk[tid];
        u64 vb = src[other * 512 + 511 - tid];
        __syncthreads();
        sk[tid] = (va > vb) ? va : vb;
        for (int j = 256; j > 0; j >>= 1) {
            __syncthreads();
            if (tid < 256) {
                int i = ((tid & ~(j - 1)) << 1) | (tid & (j - 1));
                u64 x = sk[i], y = sk[i + j];
                if (x < y) { sk[i] = y; sk[i + j] = x; }
            }
        }
    }
    __syncthreads();

    if (tid < KSEL) {
        int sel = (int)(0xFFFFFFFFu - (u32)(sk[tid] & 0xFFFFFFFFull));
        int n = b * KSEL + tid;
        g_sel[n] = sel;
        int a = sel % 9;
        int slot = atomicAdd(&g_cnt[a], 1);
        g_list[a * NSEL + slot] = n;
    }
}

// ---------------- kernel 5: anchor-grouped gather + 256x256 matvec (16 rows/block) ---
__global__ void __launch_bounds__(256)
k_post(const float* __restrict__ fm0, const float* __restrict__ fm1,
       const float* __restrict__ fm2, const float* __restrict__ fm3,
       const float* __restrict__ fm4, const float* __restrict__ w_post,
       const float* __restrict__ b_post, float* __restrict__ out) {
    __shared__ float xs[16 * 256];
    const int a = blockIdx.y;
    const int start = blockIdx.x * 16;
    const int cnt = g_cnt[a];
    if (start >= cnt) return;
    const int tid = threadIdx.x;
    const int nr = min(16, cnt - start);

#pragma unroll
    for (int r = 0; r < 16; ++r) xs[r * 256 + tid] = 0.f;

    int rows[16];
    for (int r = 0; r < nr; ++r) {
        int n = g_list[a * NSEL + start + r];
        rows[r] = n;
        int b = n / KSEL;
        int pos = g_sel[n] / 9;
        int m, hw, HW;
        if (pos < 16384)      { m = 0; hw = pos;         HW = 16384; }
        else if (pos < 20480) { m = 1; hw = pos - 16384; HW = 4096;  }
        else if (pos < 21504) { m = 2; hw = pos - 20480; HW = 1024;  }
        else if (pos < 21760) { m = 3; hw = pos - 21504; HW = 256;   }
        else                  { m = 4; hw = pos - 21760; HW = 64;    }
        const float* fm = (m == 0) ? fm0 : (m == 1) ? fm1 : (m == 2) ? fm2 : (m == 3) ? fm3 : fm4;
        xs[r * 256 + tid] = fm[((size_t)b * 256 + tid) * HW + hw];
    }
    __syncthreads();

    const float* W = w_post + (size_t)a * 65536;
    const float bb = b_post[a * 256 + tid];
    float acc[16];
#pragma unroll
    for (int r = 0; r < 16; ++r) acc[r] = bb;

#pragma unroll 2
    for (int d = 0; d < 256; ++d) {
        float w = W[d * 256 + tid];
#pragma unroll
        for (int r = 0; r < 16; ++r)
            acc[r] = fmaf(xs[r * 256 + d], w, acc[r]);
    }
    for (int r = 0; r < nr; ++r)
        out[(size_t)rows[r] * 256 + tid] = acc[r];
}

// ---------------- launch ----------------
extern "C" void kernel_launch(void* const* d_in, const int* in_sizes, int n_in,
                              void* d_out, int out_size) {
    const float* fm[5];
    for (int i = 0; i < 5; ++i) fm[i] = (const float*)d_in[i];
    const float* w_pre  = (const float*)d_in[5];
    const float* b_pre  = (const float*)d_in[6];
    const float* w_proj = (const float*)d_in[7];
    const float* b_proj = (const float*)d_in[8];
    const float* w_post = (const float*)d_in[9];
    const float* b_post = (const float*)d_in[10];
    float* out = (float*)d_out;

    const int convSmem = (2 * IB_FLOATS + 2 * WB_FLOATS) * 4;   // 81408 B
    const int top2aSmem = 8 * 512 * 8;                          // 32768 B
    cudaFuncSetAttribute(k_conv, cudaFuncAttributeMaxDynamicSharedMemorySize, convSmem);
    cudaFuncSetAttribute(k_top2a, cudaFuncAttributeMaxDynamicSharedMemorySize, top2aSmem);

    k_wtrans<<<576, 1024>>>(w_pre);

    {
        dim3 grid(341, BB, 2);   // tiles x batch x oc-half
        k_conv<<<grid, 256, convSmem>>>(fm[0], fm[1], fm[2], fm[3], fm[4], b_pre, w_proj);
    }
    {
        dim3 grid(NCHUNK, BB);
        k_top1<<<grid, 512>>>(b_proj);
    }
    {
        dim3 grid(3, BB);
        k_top2a<<<grid, 1024, top2aSmem>>>();
    }
    k_top2b<<<BB, 512>>>();
    {
        dim3 grid((NSEL + 15) / 16, 9);
        k_post<<<grid, 256>>>(fm[0], fm[1], fm[2], fm[3], fm[4], w_post, b_post, out);
    }
}